// round 11
// baseline (speedup 1.0000x reference)
#include <cuda_runtime.h>
#include <cstdint>

// YOLO-v1 loss, fused single-pass reduction.
// R11: persistent CTAs + cp.async.bulk (DMA) 3-stage pipeline with mbarrier
// completion. One elected thread issues 2 bulk copies per tile; all threads
// wait on mbarrier parity; one __syncthreads per tile orders buffer reuse.

static constexpr int CH   = 30;   // C + 5*B
static constexpr int TILE = 128;  // cells per pipeline stage
static constexpr int TPB  = 256;  // threads per block
static constexpr int STAGE_FLOATS = TILE * CH;              // 3840
static constexpr int STAGE_BYTES  = STAGE_FLOATS * 4;       // 15360 (16B mult)
static constexpr int NSTAGE = 3;
static constexpr int GRID = 304;  // 152 SMs * 2 resident CTAs (92KB smem each)

__global__ void zero_kernel(float* out) { out[0] = 0.0f; }

__device__ __forceinline__ void mbar_init(uint32_t mbar, uint32_t count) {
    asm volatile("mbarrier.init.shared.b64 [%0], %1;" :: "r"(mbar), "r"(count) : "memory");
}
__device__ __forceinline__ void mbar_expect_tx(uint32_t mbar, uint32_t bytes) {
    asm volatile("mbarrier.arrive.expect_tx.release.cta.shared::cta.b64 _, [%0], %1;"
                 :: "r"(mbar), "r"(bytes) : "memory");
}
__device__ __forceinline__ void mbar_wait(uint32_t mbar, uint32_t phase) {
    asm volatile(
        "{\n\t"
        ".reg .pred P;\n"
        "W_%=:\n\t"
        "mbarrier.try_wait.parity.acquire.cta.shared::cta.b64 P, [%0], %1, 0x989680;\n\t"
        "@P bra D_%=;\n\t"
        "bra W_%=;\n"
        "D_%=:\n\t"
        "}"
        :: "r"(mbar), "r"(phase) : "memory");
}
__device__ __forceinline__ void bulk_g2s(uint32_t dst, const void* src,
                                         uint32_t bytes, uint32_t mbar) {
    asm volatile(
        "cp.async.bulk.shared::cta.global.mbarrier::complete_tx::bytes [%0], [%1], %2, [%3];"
        :: "r"(dst), "l"(src), "r"(bytes), "r"(mbar) : "memory");
}

__device__ __forceinline__ float iou_f(
    float ax, float ay, float aw, float ah,
    float bx, float by, float bw, float bh)
{
    float ax1 = ax - aw * 0.5f, ay1 = ay - ah * 0.5f;
    float ax2 = ax + aw * 0.5f, ay2 = ay + ah * 0.5f;
    float bx1 = bx - bw * 0.5f, by1 = by - bh * 0.5f;
    float bx2 = bx + bw * 0.5f, by2 = by + bh * 0.5f;
    float x1 = fmaxf(ax1, bx1), y1 = fmaxf(ay1, by1);
    float x2 = fminf(ax2, bx2), y2 = fminf(ay2, by2);
    float inter = fmaxf(x2 - x1, 0.0f) * fmaxf(y2 - y1, 0.0f);
    float aa = fabsf((ax2 - ax1) * (ay2 - ay1));
    float ab = fabsf((bx2 - bx1) * (by2 - by1));
    return inter / (aa + ab - inter + 1e-6f);
}

extern __shared__ float smem_dyn[];  // [NSTAGE][2 tensors][STAGE_FLOATS]

// Elected-thread issue of one tile into stage s (expect_tx + tail + 2 bulks).
__device__ __forceinline__ void issue_tile(
    const float* __restrict__ pred, const float* __restrict__ targ,
    uint32_t ps_s, uint32_t ts_s, float* ps_f, float* ts_f,
    long tile, int ncells, uint32_t mbar)
{
    long cbase = tile * TILE;
    int  cells = ncells - (int)cbase;
    if (cells > TILE) cells = TILE;
    uint32_t nbytes = (uint32_t)(cells * CH) * 4u;
    uint32_t bulk   = nbytes & ~15u;          // 16B multiple for bulk copy

    const float* pg = pred + cbase * CH;
    const float* tg = targ + cbase * CH;

    // tail floats (<=2 per tensor, only possible on a ragged last tile);
    // plain smem stores, ordered for waiters by the release-arrive below.
    for (uint32_t b = bulk; b < nbytes; b += 4) {
        ps_f[b >> 2] = pg[b >> 2];
        ts_f[b >> 2] = tg[b >> 2];
    }

    mbar_expect_tx(mbar, 2u * bulk);
    bulk_g2s(ps_s, pg, bulk, mbar);
    bulk_g2s(ts_s, tg, bulk, mbar);
}

__device__ __forceinline__ float compute_tile(
    const float* __restrict__ pbuf, const float* __restrict__ tbuf,
    long tile, int ncells)
{
    long cbase = tile * TILE;
    int  cells = ncells - (int)cbase;
    if (cells > TILE) cells = TILE;
    if ((int)threadIdx.x >= cells) return 0.0f;

    const float* p = pbuf + threadIdx.x * CH;
    const float* t = tbuf + threadIdx.x * CH;

    float t20 = t[20];
    float t21 = t[21], t22 = t[22], t23 = t[23], t24 = t[24];
    float iou1 = iou_f(p[21], p[22], p[23], p[24], t21, t22, t23, t24);
    float iou2 = iou_f(p[26], p[27], p[28], p[29], t21, t22, t23, t24);

    // bestbox selects p[29] (as written in the reference) else p[20]
    float pc = (iou2 > iou1) ? p[29] : p[20];
    float e  = t20;
    float no = 1.0f - e;

    float d = e * pc - e * t20;          // obj loss
    float acc = d * d;

    d = no * p[20] - no * t20; float nl = d * d;   // noobj (x0.5)
    d = no * p[29] - no * t20; nl += d * d;
    acc += 0.5f * nl;

    float cl = 0.0f;                      // class loss
    #pragma unroll
    for (int k = 0; k < 20; k++) {
        float dd = e * p[k] - e * t[k];
        cl += dd * dd;
    }
    acc += cl;
    // box_loss == 0 in the reference; LAMBDA_COORD term drops out.
    return acc;
}

__global__ __launch_bounds__(TPB) void yolo_loss_kernel(
    const float* __restrict__ pred, const float* __restrict__ targ,
    float* __restrict__ out, int ncells, int ntiles)
{
    __shared__ __align__(8) uint64_t mbar_store[NSTAGE];

    float* pb[NSTAGE];
    float* tb[NSTAGE];
    uint32_t ps_s[NSTAGE], ts_s[NSTAGE], mb[NSTAGE];
    #pragma unroll
    for (int s = 0; s < NSTAGE; s++) {
        pb[s] = smem_dyn + (2 * s)     * STAGE_FLOATS;
        tb[s] = smem_dyn + (2 * s + 1) * STAGE_FLOATS;
        ps_s[s] = (uint32_t)__cvta_generic_to_shared(pb[s]);
        ts_s[s] = (uint32_t)__cvta_generic_to_shared(tb[s]);
        mb[s]   = (uint32_t)__cvta_generic_to_shared(&mbar_store[s]);
    }

    if (threadIdx.x == 0) {
        #pragma unroll
        for (int s = 0; s < NSTAGE; s++) mbar_init(mb[s], 1);
    }
    __syncthreads();

    long t0 = blockIdx.x;

    // Prologue: issue up to NSTAGE tiles.
    if (threadIdx.x == 0) {
        #pragma unroll
        for (int s = 0; s < NSTAGE; s++) {
            long tl = t0 + (long)s * gridDim.x;
            if (tl < ntiles)
                issue_tile(pred, targ, ps_s[s], ts_s[s], pb[s], tb[s],
                           tl, ncells, mb[s]);
        }
    }

    float acc = 0.0f;
    int it = 0;
    for (long tile = t0; tile < ntiles; tile += gridDim.x, it++) {
        int s = it % NSTAGE;
        uint32_t phase = (uint32_t)((it / NSTAGE) & 1);

        mbar_wait(mb[s], phase);                 // data for this tile ready
        acc += compute_tile(pb[s], tb[s], tile, ncells);
        __syncthreads();                          // all threads done reading s

        long nxt = tile + (long)NSTAGE * gridDim.x;
        if (nxt < ntiles && threadIdx.x == 0)
            issue_tile(pred, targ, ps_s[s], ts_s[s], pb[s], tb[s],
                       nxt, ncells, mb[s]);
    }

    // final reduction: warp shuffle -> block -> one atomic per block
    #pragma unroll
    for (int off = 16; off; off >>= 1)
        acc += __shfl_down_sync(0xffffffffu, acc, off);

    __shared__ float wsum[TPB / 32];
    int wid = threadIdx.x >> 5, lid = threadIdx.x & 31;
    if (lid == 0) wsum[wid] = acc;
    __syncthreads();
    if (wid == 0) {
        float v = (lid < TPB / 32) ? wsum[lid] : 0.0f;
        #pragma unroll
        for (int off = 4; off; off >>= 1)
            v += __shfl_down_sync(0xffffffffu, v, off);
        if (lid == 0) atomicAdd(out, v);
    }
}

extern "C" void kernel_launch(void* const* d_in, const int* in_sizes, int n_in,
                              void* d_out, int out_size)
{
    const float* pred = (const float*)d_in[0];
    const float* targ = (const float*)d_in[1];
    float* out = (float*)d_out;

    int ncells = in_sizes[0] / CH;
    int ntiles = (ncells + TILE - 1) / TILE;
    size_t shmem = (size_t)(2 * NSTAGE * STAGE_FLOATS) * sizeof(float); // 92160 B

    cudaFuncSetAttribute(yolo_loss_kernel,
                         cudaFuncAttributeMaxDynamicSharedMemorySize, (int)shmem);

    int nblocks = GRID < ntiles ? GRID : ntiles;
    zero_kernel<<<1, 1>>>(out);
    yolo_loss_kernel<<<nblocks, TPB, shmem>>>(pred, targ, out, ncells, ntiles);
}